// round 5
// baseline (speedup 1.0000x reference)
#include <cuda_runtime.h>
#include <cuda_bf16.h>

typedef unsigned long long u64;

// ---------------- f32x2 helpers (Blackwell packed fp32) ----------------
__device__ __forceinline__ void fma2(u64& d, u64 a, u64 b) {
    asm("fma.rn.f32x2 %0, %1, %2, %0;" : "+l"(d) : "l"(a), "l"(b));
}
__device__ __forceinline__ void mul2(u64& d, u64 a) {
    asm("mul.rn.f32x2 %0, %0, %1;" : "+l"(d) : "l"(a));
}
__device__ __forceinline__ u64 pk2(float x, float y) {
    u64 r; asm("mov.b64 %0, {%1, %2};" : "=l"(r) : "f"(x), "f"(y)); return r;
}
__device__ __forceinline__ float2 upk(u64 v) {
    float2 r; asm("mov.b64 {%0, %1}, %2;" : "=f"(r.x), "=f"(r.y) : "l"(v)); return r;
}

// ---------------- problem constants ----------------
#define BB   4
#define LL   2048
#define DMODEL 1024
#define NH   16
#define DH   64
#define M_ROWS (BB*LL)          // 8192
#define QKV_N  (3*DMODEL)       // 3072

// ---------------- scratch (device globals; no allocation allowed) ----------------
__device__ float g_qkv[(size_t)M_ROWS * QKV_N];   // 96 MB
__device__ float g_att[(size_t)M_ROWS * DMODEL];  // 32 MB
__device__ float g_prj[(size_t)M_ROWS * DMODEL];  // 32 MB

// =====================================================================
// SGEMM (TN): C[m,n] = sum_k A[m,k]*B[n,k] + bias[n]
// A: M x K row-major, B: N x K row-major. M,N multiples of 128, K of 8.
// 128x128x8 tile, 256 threads, 8x8 per thread, f32x2 accumulation.
// =====================================================================
__global__ __launch_bounds__(256) void sgemm_tn(
    const float* __restrict__ A, const float* __restrict__ B,
    const float* __restrict__ bias, float* __restrict__ C,
    int M, int N, int K)
{
    __shared__ float As[8][128];
    __shared__ float Bs[8][128];
    const int tid = threadIdx.x;
    const int bm = blockIdx.y * 128;
    const int bn = blockIdx.x * 128;
    const int lr = tid >> 1;            // 0..127
    const int lc = (tid & 1) * 4;       // 0 or 4
    const float* Ap = A + (long)(bm + lr) * K + lc;
    const float* Bp = B + (long)(bn + lr) * K + lc;
    const int tm = (tid >> 4) * 8;
    const int tn = (tid & 15) * 8;

    u64 acc[8][4];
#pragma unroll
    for (int i = 0; i < 8; i++)
#pragma unroll
        for (int j = 0; j < 4; j++) acc[i][j] = 0ull;

    for (int k0 = 0; k0 < K; k0 += 8) {
        float4 a4 = *(const float4*)(Ap + k0);
        float4 b4 = *(const float4*)(Bp + k0);
        __syncthreads();
        As[lc + 0][lr] = a4.x; As[lc + 1][lr] = a4.y;
        As[lc + 2][lr] = a4.z; As[lc + 3][lr] = a4.w;
        Bs[lc + 0][lr] = b4.x; Bs[lc + 1][lr] = b4.y;
        Bs[lc + 2][lr] = b4.z; Bs[lc + 3][lr] = b4.w;
        __syncthreads();
#pragma unroll
        for (int kk = 0; kk < 8; kk++) {
            float4 x0 = *(const float4*)&As[kk][tm];
            float4 x1 = *(const float4*)&As[kk][tm + 4];
            float4 y0 = *(const float4*)&Bs[kk][tn];
            float4 y1 = *(const float4*)&Bs[kk][tn + 4];
            u64 bb[4] = { pk2(y0.x, y0.y), pk2(y0.z, y0.w),
                          pk2(y1.x, y1.y), pk2(y1.z, y1.w) };
            float xa[8] = { x0.x, x0.y, x0.z, x0.w, x1.x, x1.y, x1.z, x1.w };
#pragma unroll
            for (int i = 0; i < 8; i++) {
                u64 ap = pk2(xa[i], xa[i]);
#pragma unroll
                for (int j = 0; j < 4; j++) fma2(acc[i][j], ap, bb[j]);
            }
        }
    }

    float bi[8];
#pragma unroll
    for (int j = 0; j < 8; j++) bi[j] = bias[bn + tn + j];
#pragma unroll
    for (int i = 0; i < 8; i++) {
        float* Cp = C + (long)(bm + tm + i) * N + bn + tn;
        float2 t0 = upk(acc[i][0]), t1 = upk(acc[i][1]);
        float2 t2 = upk(acc[i][2]), t3 = upk(acc[i][3]);
        float4 o0 = make_float4(t0.x + bi[0], t0.y + bi[1], t1.x + bi[2], t1.y + bi[3]);
        float4 o1 = make_float4(t2.x + bi[4], t2.y + bi[5], t3.x + bi[6], t3.y + bi[7]);
        *(float4*)Cp = o0;
        *(float4*)(Cp + 4) = o1;
    }
}

// =====================================================================
// q/k RMS norm over flattened 1024 channels, in place on qkv buffer.
// q <- q * g_q * 4 / max(||q||, eps)    (4 = sqrt(1024)/sqrt(64))
// k <- k * g_k * 32 / max(||k||, eps)
// One block per token row, 256 threads (1024 floats = 256 float4 each side).
// =====================================================================
__global__ __launch_bounds__(256) void qk_norm_kernel(
    float* __restrict__ qkv, const float* __restrict__ gq, const float* __restrict__ gk)
{
    long row = blockIdx.x;
    float* p = qkv + row * (long)QKV_N;
    int c = threadIdx.x * 4;
    float4 q4 = *(float4*)(p + c);
    float4 k4 = *(float4*)(p + DMODEL + c);
    float sq = q4.x * q4.x + q4.y * q4.y + q4.z * q4.z + q4.w * q4.w;
    float sk = k4.x * k4.x + k4.y * k4.y + k4.z * k4.z + k4.w * k4.w;
#pragma unroll
    for (int m = 16; m; m >>= 1) {
        sq += __shfl_xor_sync(0xffffffffu, sq, m);
        sk += __shfl_xor_sync(0xffffffffu, sk, m);
    }
    __shared__ float2 ws[8];
    __shared__ float2 fac;
    int w = threadIdx.x >> 5;
    if ((threadIdx.x & 31) == 0) ws[w] = make_float2(sq, sk);
    __syncthreads();
    if (threadIdx.x == 0) {
        float a = 0.f, b = 0.f;
#pragma unroll
        for (int i = 0; i < 8; i++) { a += ws[i].x; b += ws[i].y; }
        fac = make_float2(4.0f / fmaxf(sqrtf(a), 1e-12f),
                          32.0f / fmaxf(sqrtf(b), 1e-12f));
    }
    __syncthreads();
    float fq = fac.x, fk = fac.y;
    float4 gq4 = *(const float4*)(gq + c);
    float4 gk4 = *(const float4*)(gk + c);
    q4.x *= fq * gq4.x; q4.y *= fq * gq4.y; q4.z *= fq * gq4.z; q4.w *= fq * gq4.w;
    k4.x *= fk * gk4.x; k4.y *= fk * gk4.y; k4.z *= fk * gk4.z; k4.w *= fk * gk4.w;
    *(float4*)(p + c) = q4;
    *(float4*)(p + DMODEL + c) = k4;
}

// =====================================================================
// Flash attention, fp32, full (non-causal) softmax.
// Grid: (L/64, B*NH). 256 threads = 16x16; each thread owns 4 query rows
// x 4 key cols (S) and 4 query rows x 4 d cols (O). f32x2 accumulation.
// smem: Qs[d][row], Ks[d][key] (overlaid by Ps[key][row]), Vs[key][d],
// all padded stride 68 -> 52224 B dynamic.
// =====================================================================
#define ASTR 68
#define FA_SMEM (3 * 64 * ASTR * 4)

__global__ __launch_bounds__(256) void flash_attn(
    const float* __restrict__ qkv, float* __restrict__ outp)
{
    extern __shared__ float sm[];
    float* Qs = sm;                  // [64][ASTR] : Qs[d*ASTR + row]
    float* Ks = sm + 64 * ASTR;      // [64][ASTR] : Ks[d*ASTR + key]; reused as Ps[key][row]
    float* Vs = sm + 2 * 64 * ASTR;  // [64][ASTR] : Vs[key*ASTR + d]
    float* Ps = Ks;

    const int tid = threadIdx.x;
    const int ty = tid >> 4, tx = tid & 15;
    const int ty4 = ty * 4, tx4 = tx * 4;
    const int bh = blockIdx.y;
    const long base = ((long)(bh >> 4)) * ((long)LL * QKV_N) + (long)(bh & 15) * DH;
    const int q0 = blockIdx.x * 64;

    // Load Q transposed (key-fast mapping: conflict-free STS)
#pragma unroll
    for (int it = 0; it < 4; it++) {
        int idx = it * 256 + tid;
        int row = idx & 63;
        int d4 = (idx >> 6) << 2;
        float4 v = *(const float4*)(qkv + base + (long)(q0 + row) * QKV_N + d4);
        Qs[(d4 + 0) * ASTR + row] = v.x; Qs[(d4 + 1) * ASTR + row] = v.y;
        Qs[(d4 + 2) * ASTR + row] = v.z; Qs[(d4 + 3) * ASTR + row] = v.w;
    }

    float mrow[4], lrow[4];
    u64 o2[4][2];
#pragma unroll
    for (int i = 0; i < 4; i++) { mrow[i] = -1e30f; lrow[i] = 0.f; o2[i][0] = 0ull; o2[i][1] = 0ull; }

    for (int kv0 = 0; kv0 < LL; kv0 += 64) {
        __syncthreads();   // previous PV reads done (also covers Q-load on iter 0)
        // K transposed
#pragma unroll
        for (int it = 0; it < 4; it++) {
            int idx = it * 256 + tid;
            int key = idx & 63;
            int d4 = (idx >> 6) << 2;
            float4 v = *(const float4*)(qkv + base + DMODEL + (long)(kv0 + key) * QKV_N + d4);
            Ks[(d4 + 0) * ASTR + key] = v.x; Ks[(d4 + 1) * ASTR + key] = v.y;
            Ks[(d4 + 2) * ASTR + key] = v.z; Ks[(d4 + 3) * ASTR + key] = v.w;
        }
        // V direct copy
#pragma unroll
        for (int it = 0; it < 4; it++) {
            int idx = it * 256 + tid;
            int d4 = (idx & 15) << 2;
            int key = idx >> 4;
            float4 v = *(const float4*)(qkv + base + 2 * DMODEL + (long)(kv0 + key) * QKV_N + d4);
            *(float4*)&Vs[key * ASTR + d4] = v;
        }
        __syncthreads();

        // S = Q K^T (4x4 per thread, f32x2 pairs along keys)
        u64 s2[4][2];
#pragma unroll
        for (int i = 0; i < 4; i++) { s2[i][0] = 0ull; s2[i][1] = 0ull; }
#pragma unroll 8
        for (int d = 0; d < 64; d++) {
            float4 q4 = *(const float4*)&Qs[d * ASTR + ty4];
            float4 k4 = *(const float4*)&Ks[d * ASTR + tx4];
            u64 kb0 = pk2(k4.x, k4.y), kb1 = pk2(k4.z, k4.w);
            u64 a;
            a = pk2(q4.x, q4.x); fma2(s2[0][0], a, kb0); fma2(s2[0][1], a, kb1);
            a = pk2(q4.y, q4.y); fma2(s2[1][0], a, kb0); fma2(s2[1][1], a, kb1);
            a = pk2(q4.z, q4.z); fma2(s2[2][0], a, kb0); fma2(s2[2][1], a, kb1);
            a = pk2(q4.w, q4.w); fma2(s2[3][0], a, kb0); fma2(s2[3][1], a, kb1);
        }

        // online softmax per query row (reduce over 16 tx lanes)
        float p[4][4];
#pragma unroll
        for (int i = 0; i < 4; i++) {
            float2 u0 = upk(s2[i][0]), u1 = upk(s2[i][1]);
            float s0 = u0.x, s1 = u0.y, sv2 = u1.x, s3 = u1.y;
            float mx = fmaxf(fmaxf(s0, s1), fmaxf(sv2, s3));
            mx = fmaxf(mx, __shfl_xor_sync(0xffffffffu, mx, 1));
            mx = fmaxf(mx, __shfl_xor_sync(0xffffffffu, mx, 2));
            mx = fmaxf(mx, __shfl_xor_sync(0xffffffffu, mx, 4));
            mx = fmaxf(mx, __shfl_xor_sync(0xffffffffu, mx, 8));
            float mnew = fmaxf(mrow[i], mx);
            float alpha = __expf(mrow[i] - mnew);
            p[i][0] = __expf(s0 - mnew);
            p[i][1] = __expf(s1 - mnew);
            p[i][2] = __expf(sv2 - mnew);
            p[i][3] = __expf(s3 - mnew);
            float rs = p[i][0] + p[i][1] + p[i][2] + p[i][3];
            rs += __shfl_xor_sync(0xffffffffu, rs, 1);
            rs += __shfl_xor_sync(0xffffffffu, rs, 2);
            rs += __shfl_xor_sync(0xffffffffu, rs, 4);
            rs += __shfl_xor_sync(0xffffffffu, rs, 8);
            lrow[i] = lrow[i] * alpha + rs;
            mrow[i] = mnew;
            u64 a2 = pk2(alpha, alpha);
            mul2(o2[i][0], a2);
            mul2(o2[i][1], a2);
        }

        __syncthreads();   // everyone finished reading Ks before P overlay
#pragma unroll
        for (int j = 0; j < 4; j++) {
            *(float4*)&Ps[(tx4 + j) * ASTR + ty4] =
                make_float4(p[0][j], p[1][j], p[2][j], p[3][j]);
        }
        __syncthreads();

        // O += P V (f32x2 pairs along d)
#pragma unroll 8
        for (int kk = 0; kk < 64; kk++) {
            float4 pv = *(const float4*)&Ps[kk * ASTR + ty4];
            float4 v4 = *(const float4*)&Vs[kk * ASTR + tx4];
            u64 vb0 = pk2(v4.x, v4.y), vb1 = pk2(v4.z, v4.w);
            u64 a;
            a = pk2(pv.x, pv.x); fma2(o2[0][0], a, vb0); fma2(o2[0][1], a, vb1);
            a = pk2(pv.y, pv.y); fma2(o2[1][0], a, vb0); fma2(o2[1][1], a, vb1);
            a = pk2(pv.z, pv.z); fma2(o2[2][0], a, vb0); fma2(o2[2][1], a, vb1);
            a = pk2(pv.w, pv.w); fma2(o2[3][0], a, vb0); fma2(o2[3][1], a, vb1);
        }
    }

    // epilogue: write (b, l, h*64+d) layout
    const long ob = ((long)(bh >> 4) * LL) * DMODEL + (long)(bh & 15) * DH;
#pragma unroll
    for (int i = 0; i < 4; i++) {
        float inv = 1.0f / lrow[i];
        float2 u0 = upk(o2[i][0]), u1 = upk(o2[i][1]);
        float4 o = make_float4(u0.x * inv, u0.y * inv, u1.x * inv, u1.y * inv);
        *(float4*)(outp + ob + (long)(q0 + ty4 + i) * DMODEL + tx4) = o;
    }
}

// =====================================================================
// Final RMS norm: out = y * g_out * 32 / max(||y||, eps), one block/row.
// =====================================================================
__global__ __launch_bounds__(256) void final_norm_kernel(
    const float* __restrict__ in, const float* __restrict__ g, float* __restrict__ outp)
{
    long row = blockIdx.x;
    const float* p = in + row * (long)DMODEL;
    int c = threadIdx.x * 4;
    float4 v = *(const float4*)(p + c);
    float s = v.x * v.x + v.y * v.y + v.z * v.z + v.w * v.w;
#pragma unroll
    for (int m = 16; m; m >>= 1) s += __shfl_xor_sync(0xffffffffu, s, m);
    __shared__ float ws[8];
    __shared__ float fac;
    int w = threadIdx.x >> 5;
    if ((threadIdx.x & 31) == 0) ws[w] = s;
    __syncthreads();
    if (threadIdx.x == 0) {
        float a = 0.f;
#pragma unroll
        for (int i = 0; i < 8; i++) a += ws[i];
        fac = 32.0f / fmaxf(sqrtf(a), 1e-12f);
    }
    __syncthreads();
    float f = fac;
    float4 g4 = *(const float4*)(g + c);
    float4 o = make_float4(v.x * f * g4.x, v.y * f * g4.y, v.z * f * g4.z, v.w * f * g4.w);
    *(float4*)(outp + row * (long)DMODEL + c) = o;
}

// =====================================================================
// launch
// =====================================================================
extern "C" void kernel_launch(void* const* d_in, const int* in_sizes, int n_in,
                              void* d_out, int out_size)
{
    const float* x    = (const float*)d_in[0];
    const float* Wqkv = (const float*)d_in[1];
    const float* bqkv = (const float*)d_in[2];
    const float* Wout = (const float*)d_in[3];
    const float* bout = (const float*)d_in[4];
    const float* gq   = (const float*)d_in[5];
    const float* gk   = (const float*)d_in[6];
    const float* gout = (const float*)d_in[7];
    float* out = (float*)d_out;

    float *qkv, *att, *prj;
    cudaGetSymbolAddress((void**)&qkv, g_qkv);
    cudaGetSymbolAddress((void**)&att, g_att);
    cudaGetSymbolAddress((void**)&prj, g_prj);

    // 1) QKV projection
    sgemm_tn<<<dim3(QKV_N / 128, M_ROWS / 128), 256>>>(x, Wqkv, bqkv, qkv,
                                                       M_ROWS, QKV_N, DMODEL);
    // 2) q/k RMS norm (in place, folds scales)
    qk_norm_kernel<<<M_ROWS, 256>>>(qkv, gq, gk);
    // 3) attention
    cudaFuncSetAttribute(flash_attn, cudaFuncAttributeMaxDynamicSharedMemorySize, FA_SMEM);
    flash_attn<<<dim3(LL / 64, BB * NH), 256, FA_SMEM>>>(qkv, att);
    // 4) output projection
    sgemm_tn<<<dim3(DMODEL / 128, M_ROWS / 128), 256>>>(att, Wout, bout, prj,
                                                        M_ROWS, DMODEL, DMODEL);
    // 5) final RMS norm -> d_out
    final_norm_kernel<<<M_ROWS, 256>>>(prj, gout, out);
}

// round 8
// speedup vs baseline: 2.7246x; 2.7246x over previous
#include <cuda_runtime.h>
#include <cuda_fp16.h>

typedef unsigned int u32;
typedef unsigned long long u64;

// ---------------- problem constants ----------------
#define BB 4
#define LL 2048
#define DM 1024
#define NH 16
#define MR 8192
#define N3 3072

// ---------------- scratch (device globals; allocation is forbidden) ----------------
__device__ float g_qkv[(size_t)MR * N3];
__device__ float g_prj[(size_t)MR * DM];
__device__ __half g_xhi[(size_t)MR * DM],  g_xlo[(size_t)MR * DM];
__device__ __half g_whi[(size_t)N3 * DM],  g_wlo[(size_t)N3 * DM];
__device__ __half g_wohi[(size_t)DM * DM], g_wolo[(size_t)DM * DM];
__device__ __half g_qhi[(size_t)MR * DM],  g_qlo[(size_t)MR * DM];
__device__ __half g_khi[(size_t)MR * DM],  g_klo[(size_t)MR * DM];
__device__ __half g_ahi[(size_t)MR * DM],  g_alo[(size_t)MR * DM];
__device__ __half g_vthi[(size_t)BB * NH * 64 * LL], g_vtlo[(size_t)BB * NH * 64 * LL];

// ---------------- portable PTX helpers (standard since sm_75/80) ----------------
__device__ __forceinline__ u32 smem_u32(const void* p) {
    u32 a;
    asm("{ .reg .u64 t; cvta.to.shared.u64 t, %1; cvt.u32.u64 %0, t; }" : "=r"(a) : "l"(p));
    return a;
}
__device__ __forceinline__ void ldsm4(u32& r0, u32& r1, u32& r2, u32& r3, u32 a) {
    asm volatile("ldmatrix.sync.aligned.m8n8.x4.shared.b16 {%0,%1,%2,%3},[%4];"
                 : "=r"(r0), "=r"(r1), "=r"(r2), "=r"(r3) : "r"(a));
}
__device__ __forceinline__ void ldsm2(u32& r0, u32& r1, u32 a) {
    asm volatile("ldmatrix.sync.aligned.m8n8.x2.shared.b16 {%0,%1},[%2];"
                 : "=r"(r0), "=r"(r1) : "r"(a));
}
__device__ __forceinline__ void mma16(float* c, const u32* a, const u32* b) {
    asm volatile("mma.sync.aligned.m16n8k16.row.col.f32.f16.f16.f32 "
                 "{%0,%1,%2,%3},{%4,%5,%6,%7},{%8,%9},{%0,%1,%2,%3};"
                 : "+f"(c[0]), "+f"(c[1]), "+f"(c[2]), "+f"(c[3])
                 : "r"(a[0]), "r"(a[1]), "r"(a[2]), "r"(a[3]), "r"(b[0]), "r"(b[1]));
}
__device__ __forceinline__ float ex2f(float x) {
    float y; asm("ex2.approx.f32 %0,%1;" : "=f"(y) : "f"(x)); return y;
}
#define CPA16(d, s) asm volatile("cp.async.cg.shared.global [%0],[%1],16;" :: "r"(d), "l"(s) : "memory")
#define CPC()       asm volatile("cp.async.commit_group;" ::: "memory")
#define CPW(n)      asm volatile("cp.async.wait_group %0;" :: "n"(n) : "memory")

// =====================================================================
// fp32 -> fp16 hi/lo planar split
// =====================================================================
__global__ __launch_bounds__(256) void conv_hilo(
    const float* __restrict__ src, __half* __restrict__ hi,
    __half* __restrict__ lo, long n4)
{
    long i = (long)blockIdx.x * 256 + threadIdx.x;
    if (i >= n4) return;
    float4 v = ((const float4*)src)[i];
    float f[4] = { v.x, v.y, v.z, v.w };
    __half h[4], l[4];
#pragma unroll
    for (int e = 0; e < 4; e++) {
        h[e] = __float2half_rn(f[e]);
        l[e] = __float2half_rn(f[e] - __half2float(h[e]));
    }
    ((uint2*)hi)[i] = *(uint2*)h;
    ((uint2*)lo)[i] = *(uint2*)l;
}

// =====================================================================
// HMMA TN GEMM, fp16 hi/lo (3 products): C = A B^T + bias, fp32 out.
// A: M x K, B: N x K (K mult of 32). 128x128 tile, 256 thr, dbl-buffered.
// smem planes per buffer: AHI, ALO, BHI, BLO each [128][40] half.
// =====================================================================
#define GSTR 40
#define GPL  5120
#define GBUF 20480
#define GM_SMEM (2 * GBUF * 2)

__global__ __launch_bounds__(256) void gemm_mma(
    const __half* __restrict__ Ahi, const __half* __restrict__ Alo,
    const __half* __restrict__ Bhi, const __half* __restrict__ Blo,
    const float* __restrict__ bias, float* __restrict__ C, int N, int K)
{
    extern __shared__ __half sh[];
    const u32 sb = smem_u32(sh);
    const int tid = threadIdx.x, w = tid >> 5, lane = tid & 31;
    const int bm = blockIdx.y * 128, bn = blockIdx.x * 128;
    const int wm = (w >> 2) * 64, wn = (w & 3) * 32;

    float acc[4][4][4];
#pragma unroll
    for (int mt = 0; mt < 4; mt++)
#pragma unroll
        for (int nt = 0; nt < 4; nt++)
#pragma unroll
            for (int r = 0; r < 4; r++) acc[mt][nt][r] = 0.f;

    // per-thread load descriptors (8 x 16B per chunk)
    const __half* lsrc[8]; u32 ldst[8];
#pragma unroll
    for (int it = 0; it < 8; it++) {
        int i = it * 256 + tid, pl = i >> 9, j = i & 511, r = j >> 2, s = j & 3;
        long grow = (pl < 2) ? (long)(bm + r) : (long)(bn + r);
        const __half* bp = (pl == 0) ? Ahi : (pl == 1) ? Alo : (pl == 2) ? Bhi : Blo;
        lsrc[it] = bp + grow * (long)K + s * 8;
        ldst[it] = (u32)((pl * GPL + r * GSTR + s * 8) * 2);
    }
    const int nch = K / 32;
#pragma unroll
    for (int it = 0; it < 8; it++) CPA16(sb + ldst[it], lsrc[it]);
    CPC();

    for (int c = 0; c < nch; c++) {
        if (c + 1 < nch) {
            u32 bo = (u32)(((c + 1) & 1) * GBUF * 2);
#pragma unroll
            for (int it = 0; it < 8; it++) CPA16(sb + bo + ldst[it], lsrc[it] + (c + 1) * 32);
            CPC();
            CPW(1);
        } else {
            CPW(0);
        }
        __syncthreads();
        u32 base = sb + (u32)((c & 1) * GBUF * 2);
#pragma unroll
        for (int ks = 0; ks < 2; ks++) {
            u32 ah[4][4], al[4][4], bh[4][2], bl[4][2];
#pragma unroll
            for (int mt = 0; mt < 4; mt++) {
                u32 ra = base + (u32)(((wm + mt * 16 + (lane & 15)) * GSTR +
                                       ks * 16 + ((lane >> 4) & 1) * 8) * 2);
                ldsm4(ah[mt][0], ah[mt][1], ah[mt][2], ah[mt][3], ra);
                ldsm4(al[mt][0], al[mt][1], al[mt][2], al[mt][3], ra + GPL * 2);
            }
#pragma unroll
            for (int nt = 0; nt < 4; nt++) {
                u32 rb = base + (u32)((2 * GPL + (wn + nt * 8 + (lane & 7)) * GSTR +
                                       ks * 16 + ((lane >> 3) & 1) * 8) * 2);
                ldsm2(bh[nt][0], bh[nt][1], rb);
                ldsm2(bl[nt][0], bl[nt][1], rb + GPL * 2);
            }
#pragma unroll
            for (int mt = 0; mt < 4; mt++)
#pragma unroll
                for (int nt = 0; nt < 4; nt++) {
                    mma16(acc[mt][nt], ah[mt], bh[nt]);
                    mma16(acc[mt][nt], ah[mt], bl[nt]);
                    mma16(acc[mt][nt], al[mt], bh[nt]);
                }
        }
        __syncthreads();
    }
    // epilogue
#pragma unroll
    for (int mt = 0; mt < 4; mt++) {
        int r0 = bm + wm + mt * 16 + (lane >> 2);
#pragma unroll
        for (int nt = 0; nt < 4; nt++) {
            int cb = bn + wn + nt * 8 + 2 * (lane & 3);
            float2 bv = *(const float2*)(bias + cb);
            float2 o0 = make_float2(acc[mt][nt][0] + bv.x, acc[mt][nt][1] + bv.y);
            float2 o1 = make_float2(acc[mt][nt][2] + bv.x, acc[mt][nt][3] + bv.y);
            *(float2*)(C + (long)r0 * N + cb) = o0;
            *(float2*)(C + (long)(r0 + 8) * N + cb) = o1;
        }
    }
}

// =====================================================================
// q/k RMS norm -> fp16 hi/lo. q folds g*4*log2(e)/||q||, k folds g*32/||k||
// =====================================================================
__global__ __launch_bounds__(256) void qk_norm(
    const float* __restrict__ qkv,
    const float* __restrict__ gq, const float* __restrict__ gk,
    __half* __restrict__ qhi, __half* __restrict__ qlo,
    __half* __restrict__ khi, __half* __restrict__ klo)
{
    long row = blockIdx.x;
    const float* p = qkv + row * (long)N3;
    int c = threadIdx.x * 4;
    float4 q4 = *(const float4*)(p + c);
    float4 k4 = *(const float4*)(p + DM + c);
    float sq = q4.x * q4.x + q4.y * q4.y + q4.z * q4.z + q4.w * q4.w;
    float sk = k4.x * k4.x + k4.y * k4.y + k4.z * k4.z + k4.w * k4.w;
#pragma unroll
    for (int m = 16; m; m >>= 1) {
        sq += __shfl_xor_sync(0xffffffffu, sq, m);
        sk += __shfl_xor_sync(0xffffffffu, sk, m);
    }
    __shared__ float2 ws[8];
    __shared__ float2 fac;
    int w = threadIdx.x >> 5;
    if ((threadIdx.x & 31) == 0) ws[w] = make_float2(sq, sk);
    __syncthreads();
    if (threadIdx.x == 0) {
        float a = 0.f, bsum = 0.f;
#pragma unroll
        for (int i = 0; i < 8; i++) { a += ws[i].x; bsum += ws[i].y; }
        fac = make_float2(5.770780163555851f / fmaxf(sqrtf(a), 1e-12f),   // 4*log2(e)
                          32.0f / fmaxf(sqrtf(bsum), 1e-12f));
    }
    __syncthreads();
    float fq = fac.x, fk = fac.y;
    float4 gq4 = *(const float4*)(gq + c);
    float4 gk4 = *(const float4*)(gk + c);
    float qs[4] = { q4.x * fq * gq4.x, q4.y * fq * gq4.y, q4.z * fq * gq4.z, q4.w * fq * gq4.w };
    float ks[4] = { k4.x * fk * gk4.x, k4.y * fk * gk4.y, k4.z * fk * gk4.z, k4.w * fk * gk4.w };
    __half qh[4], ql[4], kh[4], kl[4];
#pragma unroll
    for (int e = 0; e < 4; e++) {
        qh[e] = __float2half_rn(qs[e]); ql[e] = __float2half_rn(qs[e] - __half2float(qh[e]));
        kh[e] = __float2half_rn(ks[e]); kl[e] = __float2half_rn(ks[e] - __half2float(kh[e]));
    }
    long o = row * (long)DM + c;
    *(uint2*)(qhi + o) = *(uint2*)qh;  *(uint2*)(qlo + o) = *(uint2*)ql;
    *(uint2*)(khi + o) = *(uint2*)kh;  *(uint2*)(klo + o) = *(uint2*)kl;
}

// =====================================================================
// V transpose: qkv v-part (b,l,h*64+d) fp32 -> fp16 hi/lo [(bh*64+d)][l]
// =====================================================================
#define VT_STR 136
__global__ __launch_bounds__(256) void v_trans(
    const float* __restrict__ qkv, __half* __restrict__ vthi, __half* __restrict__ vtlo)
{
    __shared__ __half shi[64 * VT_STR], slo[64 * VT_STR];
    int bh = blockIdx.y, b = bh >> 4, h = bh & 15;
    int l0 = blockIdx.x * 128;
    int tid = threadIdx.x;
#pragma unroll
    for (int it = 0; it < 8; it++) {
        int idx = it * 256 + tid;
        int l = idx >> 4, d4 = (idx & 15) * 4;
        float4 v = *(const float4*)(qkv + ((long)(b * LL + l0 + l)) * N3 + 2 * DM + h * 64 + d4);
        float f[4] = { v.x, v.y, v.z, v.w };
#pragma unroll
        for (int e = 0; e < 4; e++) {
            __half hv = __float2half_rn(f[e]);
            __half lv = __float2half_rn(f[e] - __half2float(hv));
            shi[(d4 + e) * VT_STR + l] = hv;
            slo[(d4 + e) * VT_STR + l] = lv;
        }
    }
    __syncthreads();
#pragma unroll
    for (int it = 0; it < 8; it++) {
        int i = it * 256 + tid;
        int pl = i >> 10, j = i & 1023;
        int d = j >> 4, s = j & 15;
        uint4 v = *(uint4*)&((pl ? slo : shi)[d * VT_STR + s * 8]);
        *(uint4*)((pl ? vtlo : vthi) + ((long)bh * 64 + d) * LL + l0 + s * 8) = v;
    }
}

// =====================================================================
// HMMA flash attention. Block = (128-q tile, bh). 256 thr = 8 warps (4m x 2n).
// smem (half idx): QHI 0, QLO 9216, KHI 18432, KLO 23040, VHI 27648,
//                  VLO 32256, PHI 36864, PLO 46080; red floats at 55296.
// =====================================================================
#define AQHI 0
#define AQLO 9216
#define AKV  18432
#define APHI 36864
#define APLO 46080
#define ARED 55296
#define AT_SMEM 112640

__global__ __launch_bounds__(256) void attn_mma(
    const __half* __restrict__ qhi, const __half* __restrict__ qlo,
    const __half* __restrict__ khi, const __half* __restrict__ klo,
    const __half* __restrict__ vthi, const __half* __restrict__ vtlo,
    __half* __restrict__ ahi, __half* __restrict__ alo)
{
    extern __shared__ __half sh[];
    const u32 sb = smem_u32(sh);
    const int tid = threadIdx.x, w = tid >> 5, lane = tid & 31;
    const int bh = blockIdx.y, b = bh >> 4, hd = bh & 15;
    const int q0 = blockIdx.x * 128;
    const int wm = (w >> 1) * 32, wn = (w & 1);
    float* rmax = (float*)(sh + ARED);   // [2][128]
    float* rsum = rmax + 256;            // [2][128]

    // load Q hi/lo (stays resident)
#pragma unroll
    for (int it = 0; it < 8; it++) {
        int i = it * 256 + tid, pl = i >> 10, j = i & 1023, r = j >> 3, s = j & 7;
        const __half* sp = (pl ? qlo : qhi) + ((long)(b * LL + q0 + r)) * DM + hd * 64 + s * 8;
        CPA16(sb + (u32)((pl * 9216 + r * 72 + s * 8) * 2), sp);
    }
    CPC();

    float o[2][4][4];
#pragma unroll
    for (int mt = 0; mt < 2; mt++)
#pragma unroll
        for (int dt = 0; dt < 4; dt++)
#pragma unroll
            for (int r = 0; r < 4; r++) o[mt][dt][r] = 0.f;
    float mr[4] = { -1e30f, -1e30f, -1e30f, -1e30f }, lr[4] = { 0.f, 0.f, 0.f, 0.f };

    for (int c = 0; c < 32; c++) {
        const int kv0 = c * 64;
        __syncthreads();   // previous chunk's K/V/P reads complete
        // load K hi/lo + Vt hi/lo (4 planes x 64 rows x 8 segs)
#pragma unroll
        for (int it = 0; it < 8; it++) {
            int i = it * 256 + tid, pl = i >> 9, j = i & 511, r = j >> 3, s = j & 7;
            const __half* sp;
            if (pl == 0)      sp = khi  + ((long)(b * LL + kv0 + r)) * DM + hd * 64 + s * 8;
            else if (pl == 1) sp = klo  + ((long)(b * LL + kv0 + r)) * DM + hd * 64 + s * 8;
            else if (pl == 2) sp = vthi + ((long)(bh * 64 + r)) * LL + kv0 + s * 8;
            else              sp = vtlo + ((long)(bh * 64 + r)) * LL + kv0 + s * 8;
            CPA16(sb + (u32)((AKV + pl * 4608 + r * 72 + s * 8) * 2), sp);
        }
        CPC(); CPW(0);
        __syncthreads();

        // ---- S = Q K^T (hi/lo 3 products) ----
        float s[2][4][4];
#pragma unroll
        for (int mt = 0; mt < 2; mt++)
#pragma unroll
            for (int nt = 0; nt < 4; nt++)
#pragma unroll
                for (int r = 0; r < 4; r++) s[mt][nt][r] = 0.f;
#pragma unroll
        for (int ks = 0; ks < 4; ks++) {
            u32 qh_[2][4], ql_[2][4], kh_[4][2], kl_[4][2];
#pragma unroll
            for (int mt = 0; mt < 2; mt++) {
                u32 ra = sb + (u32)(((wm + mt * 16 + (lane & 15)) * 72 +
                                     ks * 16 + ((lane >> 4) & 1) * 8) * 2);
                ldsm4(qh_[mt][0], qh_[mt][1], qh_[mt][2], qh_[mt][3], ra);
                ldsm4(ql_[mt][0], ql_[mt][1], ql_[mt][2], ql_[mt][3], ra + 9216 * 2);
            }
#pragma unroll
            for (int nt = 0; nt < 4; nt++) {
                u32 rb = sb + (u32)((AKV + (wn * 32 + nt * 8 + (lane & 7)) * 72 +
                                     ks * 16 + ((lane >> 3) & 1) * 8) * 2);
                ldsm2(kh_[nt][0], kh_[nt][1], rb);
                ldsm2(kl_[nt][0], kl_[nt][1], rb + 4608 * 2);
            }
#pragma unroll
            for (int mt = 0; mt < 2; mt++)
#pragma unroll
                for (int nt = 0; nt < 4; nt++) {
                    mma16(s[mt][nt], qh_[mt], kh_[nt]);
                    mma16(s[mt][nt], qh_[mt], kl_[nt]);
                    mma16(s[mt][nt], ql_[mt], kh_[nt]);
                }
        }

        // ---- online softmax ----
        float lmx[4], lsm[4], alpha[4];
#pragma unroll
        for (int mt = 0; mt < 2; mt++)
#pragma unroll
            for (int hh = 0; hh < 2; hh++) {
                int slot = mt * 2 + hh;
                float mx = s[mt][0][hh * 2];
#pragma unroll
                for (int nt = 0; nt < 4; nt++) {
                    mx = fmaxf(mx, s[mt][nt][hh * 2]);
                    mx = fmaxf(mx, s[mt][nt][hh * 2 + 1]);
                }
                mx = fmaxf(mx, __shfl_xor_sync(0xffffffffu, mx, 1));
                mx = fmaxf(mx, __shfl_xor_sync(0xffffffffu, mx, 2));
                lmx[slot] = mx;
                if ((lane & 3) == 0)
                    rmax[wn * 128 + wm + mt * 16 + hh * 8 + (lane >> 2)] = mx;
            }
        __syncthreads();
#pragma unroll
        for (int mt = 0; mt < 2; mt++)
#pragma unroll
            for (int hh = 0; hh < 2; hh++) {
                int slot = mt * 2 + hh;
                int rl = wm + mt * 16 + hh * 8 + (lane >> 2);
                float mn = fmaxf(mr[slot], fmaxf(lmx[slot], rmax[(1 - wn) * 128 + rl]));
                alpha[slot] = ex2f(mr[slot] - mn);
                mr[slot] = mn;
                float ssum = 0.f;
#pragma unroll
                for (int nt = 0; nt < 4; nt++) {
                    float e0 = ex2f(s[mt][nt][hh * 2] - mn);
                    float e1 = ex2f(s[mt][nt][hh * 2 + 1] - mn);
                    ssum += e0 + e1;
                    __half h0 = __float2half_rn(e0), h1 = __float2half_rn(e1);
                    __half l0 = __float2half_rn(e0 - __half2float(h0));
                    __half l1 = __float2half_rn(e1 - __half2float(h1));
                    int col = wn * 32 + nt * 8 + 2 * (lane & 3);
                    *(__half2*)(sh + APHI + rl * 72 + col) = __halves2half2(h0, h1);
                    *(__half2*)(sh + APLO + rl * 72 + col) = __halves2half2(l0, l1);
                }
                ssum += __shfl_xor_sync(0xffffffffu, ssum, 1);
                ssum += __shfl_xor_sync(0xffffffffu, ssum, 2);
                lsm[slot] = ssum;
                if ((lane & 3) == 0) rsum[wn * 128 + rl] = ssum;
            }
        __syncthreads();
#pragma unroll
        for (int mt = 0; mt < 2; mt++)
#pragma unroll
            for (int hh = 0; hh < 2; hh++) {
                int slot = mt * 2 + hh;
                int rl = wm + mt * 16 + hh * 8 + (lane >> 2);
                lr[slot] = lr[slot] * alpha[slot] + lsm[slot] + rsum[(1 - wn) * 128 + rl];
            }
        // scale O by alpha, then PV mma accumulates on top
#pragma unroll
        for (int mt = 0; mt < 2; mt++)
#pragma unroll
            for (int dt = 0; dt < 4; dt++) {
                o[mt][dt][0] *= alpha[mt * 2];     o[mt][dt][1] *= alpha[mt * 2];
                o[mt][dt][2] *= alpha[mt * 2 + 1]; o[mt][dt][3] *= alpha[mt * 2 + 1];
            }
        // ---- O += P V ----
#pragma unroll
        for (int ks = 0; ks < 4; ks++) {
            u32 ph_[2][4], pl_[2][4], vh_[4][2], vl_[4][2];
#pragma unroll
            for (int mt = 0; mt < 2; mt++) {
                u32 ra = sb + (u32)((APHI + (wm + mt * 16 + (lane & 15)) * 72 +
                                     ks * 16 + ((lane >> 4) & 1) * 8) * 2);
                ldsm4(ph_[mt][0], ph_[mt][1], ph_[mt][2], ph_[mt][3], ra);
                ldsm4(pl_[mt][0], pl_[mt][1], pl_[mt][2], pl_[mt][3], ra + 9216 * 2);
            }
#pragma unroll
            for (int dt = 0; dt < 4; dt++) {
                u32 rb = sb + (u32)((AKV + 2 * 4608 + (wn * 32 + dt * 8 + (lane & 7)) * 72 +
                                     ks * 16 + ((lane >> 3) & 1) * 8) * 2);
                ldsm2(vh_[dt][0], vh_[dt][1], rb);
                ldsm2(vl_[dt][0], vl_[dt][1], rb + 4608 * 2);
            }
#pragma unroll
            for (int mt = 0; mt < 2; mt++)
#pragma unroll
                for (int dt = 0; dt < 4; dt++) {
                    mma16(o[mt][dt], ph_[mt], vh_[dt]);
                    mma16(o[mt][dt], ph_[mt], vl_[dt]);
                    mma16(o[mt][dt], pl_[mt], vh_[dt]);
                }
        }
    }

    // epilogue: normalize, split fp16 hi/lo, store (b, l, h*64+d)
#pragma unroll
    for (int mt = 0; mt < 2; mt++)
#pragma unroll
        for (int hh = 0; hh < 2; hh++) {
            int slot = mt * 2 + hh;
            float inv = 1.0f / lr[slot];
            int row = q0 + wm + mt * 16 + hh * 8 + (lane >> 2);
#pragma unroll
            for (int dt = 0; dt < 4; dt++) {
                int col = hd * 64 + wn * 32 + dt * 8 + 2 * (lane & 3);
                float v0 = o[mt][dt][hh * 2] * inv;
                float v1 = o[mt][dt][hh * 2 + 1] * inv;
                __half h0 = __float2half_rn(v0), h1 = __float2half_rn(v1);
                __half l0 = __float2half_rn(v0 - __half2float(h0));
                __half l1 = __float2half_rn(v1 - __half2float(h1));
                long off = ((long)(b * LL + row)) * DM + col;
                *(__half2*)(ahi + off) = __halves2half2(h0, h1);
                *(__half2*)(alo + off) = __halves2half2(l0, l1);
            }
        }
}

// =====================================================================
// Final RMS norm: out = y * g_out * 32 / max(||y||, eps)
// =====================================================================
__global__ __launch_bounds__(256) void final_norm_kernel(
    const float* __restrict__ in, const float* __restrict__ g, float* __restrict__ outp)
{
    long row = blockIdx.x;
    const float* p = in + row * (long)DM;
    int c = threadIdx.x * 4;
    float4 v = *(const float4*)(p + c);
    float s = v.x * v.x + v.y * v.y + v.z * v.z + v.w * v.w;
#pragma unroll
    for (int m = 16; m; m >>= 1) s += __shfl_xor_sync(0xffffffffu, s, m);
    __shared__ float ws[8];
    __shared__ float fac;
    int w = threadIdx.x >> 5;
    if ((threadIdx.x & 31) == 0) ws[w] = s;
    __syncthreads();
    if (threadIdx.x == 0) {
        float a = 0.f;
#pragma unroll
        for (int i = 0; i < 8; i++) a += ws[i];
        fac = 32.0f / fmaxf(sqrtf(a), 1e-12f);
    }
    __syncthreads();
    float f = fac;
    float4 g4 = *(const float4*)(g + c);
    float4 o = make_float4(v.x * f * g4.x, v.y * f * g4.y, v.z * f * g4.z, v.w * f * g4.w);
    *(float4*)(outp + row * (long)DM + c) = o;
}

// =====================================================================
// launch
// =====================================================================
extern "C" void kernel_launch(void* const* d_in, const int* in_sizes, int n_in,
                              void* d_out, int out_size)
{
    const float* x    = (const float*)d_in[0];
    const float* Wqkv = (const float*)d_in[1];
    const float* bqkv = (const float*)d_in[2];
    const float* Wout = (const float*)d_in[3];
    const float* bout = (const float*)d_in[4];
    const float* gq   = (const float*)d_in[5];
    const float* gk   = (const float*)d_in[6];
    const float* gout = (const float*)d_in[7];
    float* out = (float*)d_out;

    float *qkv, *prj;
    __half *xhi, *xlo, *whi, *wlo, *wohi, *wolo;
    __half *Qhi, *Qlo, *Khi, *Klo, *Ahi, *Alo, *Vthi, *Vtlo;
    cudaGetSymbolAddress((void**)&qkv, g_qkv);
    cudaGetSymbolAddress((void**)&prj, g_prj);
    cudaGetSymbolAddress((void**)&xhi, g_xhi);   cudaGetSymbolAddress((void**)&xlo, g_xlo);
    cudaGetSymbolAddress((void**)&whi, g_whi);   cudaGetSymbolAddress((void**)&wlo, g_wlo);
    cudaGetSymbolAddress((void**)&wohi, g_wohi); cudaGetSymbolAddress((void**)&wolo, g_wolo);
    cudaGetSymbolAddress((void**)&Qhi, g_qhi);   cudaGetSymbolAddress((void**)&Qlo, g_qlo);
    cudaGetSymbolAddress((void**)&Khi, g_khi);   cudaGetSymbolAddress((void**)&Klo, g_klo);
    cudaGetSymbolAddress((void**)&Ahi, g_ahi);   cudaGetSymbolAddress((void**)&Alo, g_alo);
    cudaGetSymbolAddress((void**)&Vthi, g_vthi); cudaGetSymbolAddress((void**)&Vtlo, g_vtlo);

    cudaFuncSetAttribute(gemm_mma, cudaFuncAttributeMaxDynamicSharedMemorySize, GM_SMEM);
    cudaFuncSetAttribute(attn_mma, cudaFuncAttributeMaxDynamicSharedMemorySize, AT_SMEM);

    // 0) fp32 -> fp16 hi/lo splits
    long n_x = (long)MR * DM / 4, n_w = (long)N3 * DM / 4, n_wo = (long)DM * DM / 4;
    conv_hilo<<<(unsigned)((n_x  + 255) / 256), 256>>>(x,    xhi,  xlo,  n_x);
    conv_hilo<<<(unsigned)((n_w  + 255) / 256), 256>>>(Wqkv, whi,  wlo,  n_w);
    conv_hilo<<<(unsigned)((n_wo + 255) / 256), 256>>>(Wout, wohi, wolo, n_wo);

    // 1) QKV projection (HMMA)
    gemm_mma<<<dim3(N3 / 128, MR / 128), 256, GM_SMEM>>>(xhi, xlo, whi, wlo, bqkv, qkv, N3, DM);

    // 2) q/k norm -> fp16 hi/lo ; V -> transposed fp16 hi/lo
    qk_norm<<<MR, 256>>>(qkv, gq, gk, Qhi, Qlo, Khi, Klo);
    v_trans<<<dim3(LL / 128, BB * NH), 256>>>(qkv, Vthi, Vtlo);

    // 3) attention (HMMA)
    attn_mma<<<dim3(LL / 128, BB * NH), 256, AT_SMEM>>>(Qhi, Qlo, Khi, Klo, Vthi, Vtlo, Ahi, Alo);

    // 4) output projection (HMMA)
    gemm_mma<<<dim3(DM / 128, MR / 128), 256, GM_SMEM>>>(Ahi, Alo, wohi, wolo, bout, prj, DM, DM);

    // 5) final RMS norm -> d_out
    final_norm_kernel<<<MR, 256>>>(prj, gout, out);
}

// round 9
// speedup vs baseline: 2.7322x; 1.0028x over previous
#include <cuda_runtime.h>
#include <cuda_fp16.h>

typedef unsigned int u32;
typedef unsigned long long u64;

// ---------------- problem constants ----------------
#define BB 4
#define LL 2048
#define DM 1024
#define NH 16
#define MR 8192
#define N3 3072

// ---------------- scratch (device globals; allocation is forbidden) ----------------
__device__ float g_qkv[(size_t)MR * N3];
__device__ float g_prj[(size_t)MR * DM];
__device__ __half g_xhi[(size_t)MR * DM],  g_xlo[(size_t)MR * DM];
__device__ __half g_whi[(size_t)N3 * DM],  g_wlo[(size_t)N3 * DM];
__device__ __half g_wohi[(size_t)DM * DM], g_wolo[(size_t)DM * DM];
__device__ __half g_qhi[(size_t)MR * DM],  g_qlo[(size_t)MR * DM];
__device__ __half g_khi[(size_t)MR * DM],  g_klo[(size_t)MR * DM];
__device__ __half g_ahi[(size_t)MR * DM],  g_alo[(size_t)MR * DM];
__device__ __half g_vthi[(size_t)BB * NH * 64 * LL], g_vtlo[(size_t)BB * NH * 64 * LL];

// ---------------- portable PTX helpers ----------------
__device__ __forceinline__ u32 smem_u32(const void* p) {
    u32 a;
    asm("{ .reg .u64 t; cvta.to.shared.u64 t, %1; cvt.u32.u64 %0, t; }" : "=r"(a) : "l"(p));
    return a;
}
__device__ __forceinline__ void ldsm4(u32& r0, u32& r1, u32& r2, u32& r3, u32 a) {
    asm volatile("ldmatrix.sync.aligned.m8n8.x4.shared.b16 {%0,%1,%2,%3},[%4];"
                 : "=r"(r0), "=r"(r1), "=r"(r2), "=r"(r3) : "r"(a));
}
__device__ __forceinline__ void ldsm2(u32& r0, u32& r1, u32 a) {
    asm volatile("ldmatrix.sync.aligned.m8n8.x2.shared.b16 {%0,%1},[%2];"
                 : "=r"(r0), "=r"(r1) : "r"(a));
}
__device__ __forceinline__ void mma16(float* c, const u32* a, const u32* b) {
    asm volatile("mma.sync.aligned.m16n8k16.row.col.f32.f16.f16.f32 "
                 "{%0,%1,%2,%3},{%4,%5,%6,%7},{%8,%9},{%0,%1,%2,%3};"
                 : "+f"(c[0]), "+f"(c[1]), "+f"(c[2]), "+f"(c[3])
                 : "r"(a[0]), "r"(a[1]), "r"(a[2]), "r"(a[3]), "r"(b[0]), "r"(b[1]));
}
__device__ __forceinline__ float ex2f(float x) {
    float y; asm("ex2.approx.f32 %0,%1;" : "=f"(y) : "f"(x)); return y;
}
#define CPA16(d, s) asm volatile("cp.async.cg.shared.global [%0],[%1],16;" :: "r"(d), "l"(s) : "memory")
#define CPC()       asm volatile("cp.async.commit_group;" ::: "memory")
#define CPW(n)      asm volatile("cp.async.wait_group %0;" :: "n"(n) : "memory")

// =====================================================================
// fp32 -> fp16 hi/lo planar split
// =====================================================================
__global__ __launch_bounds__(256) void conv_hilo(
    const float* __restrict__ src, __half* __restrict__ hi,
    __half* __restrict__ lo, long n4)
{
    long i = (long)blockIdx.x * 256 + threadIdx.x;
    if (i >= n4) return;
    float4 v = ((const float4*)src)[i];
    float f[4] = { v.x, v.y, v.z, v.w };
    __half h[4], l[4];
#pragma unroll
    for (int e = 0; e < 4; e++) {
        h[e] = __float2half_rn(f[e]);
        l[e] = __float2half_rn(f[e] - __half2float(h[e]));
    }
    ((uint2*)hi)[i] = *(uint2*)h;
    ((uint2*)lo)[i] = *(uint2*)l;
}

// =====================================================================
// HMMA TN GEMM, fp16 hi/lo (3 products): C = A B^T + bias, fp32 out.
// 128x128 tile, 256 thr, K-chunk 32, double-buffered, 2 CTAs/SM.
// Loader: one plane per thread group (tid>>6), single base pointer.
// =====================================================================
#define GSTR 40
#define GPL  5120
#define GBUF 20480
#define GM_SMEM (2 * GBUF * 2)

__global__ __launch_bounds__(256, 2) void gemm_mma(
    const __half* __restrict__ Ahi, const __half* __restrict__ Alo,
    const __half* __restrict__ Bhi, const __half* __restrict__ Blo,
    const float* __restrict__ bias, float* __restrict__ C, int N, int K)
{
    extern __shared__ __half sh[];
    const u32 sb = smem_u32(sh);
    const int tid = threadIdx.x, w = tid >> 5, lane = tid & 31;
    const int bm = blockIdx.y * 128, bn = blockIdx.x * 128;
    const int wm = (w >> 2) * 64, wn = (w & 3) * 32;

    float acc[4][4][4];
#pragma unroll
    for (int mt = 0; mt < 4; mt++)
#pragma unroll
        for (int nt = 0; nt < 4; nt++)
#pragma unroll
            for (int r = 0; r < 4; r++) acc[mt][nt][r] = 0.f;

    // loader: plane pl = tid>>6 (64 thr/plane); u = tid&63: s = u&3, r0 = u>>2
    const int pl = tid >> 6, lu = tid & 63, ls = lu & 3, lr0 = lu >> 2;
    const __half* lbase = ((pl == 0) ? Ahi : (pl == 1) ? Alo : (pl == 2) ? Bhi : Blo)
                          + (long)((pl < 2 ? bm : bn) + lr0) * K + ls * 8;
    const u32 ldst0 = (u32)((pl * GPL + lr0 * GSTR + ls * 8) * 2);
    const long lrowstride = (long)16 * K;

    const int nch = K / 32;
#pragma unroll
    for (int it = 0; it < 8; it++) CPA16(sb + ldst0 + it * (16 * GSTR * 2), lbase + it * lrowstride);
    CPC();

    for (int c = 0; c < nch; c++) {
        if (c + 1 < nch) {
            u32 bo = (u32)(((c + 1) & 1) * GBUF * 2);
            const __half* src = lbase + (c + 1) * 32;
#pragma unroll
            for (int it = 0; it < 8; it++) CPA16(sb + bo + ldst0 + it * (16 * GSTR * 2), src + it * lrowstride);
            CPC();
            CPW(1);
        } else {
            CPW(0);
        }
        __syncthreads();
        u32 base = sb + (u32)((c & 1) * GBUF * 2);
#pragma unroll
        for (int ks = 0; ks < 2; ks++) {
            u32 ah[4][4], al[4][4], bh[4][2], bl[4][2];
#pragma unroll
            for (int mt = 0; mt < 4; mt++) {
                u32 ra = base + (u32)(((wm + mt * 16 + (lane & 15)) * GSTR +
                                       ks * 16 + ((lane >> 4) & 1) * 8) * 2);
                ldsm4(ah[mt][0], ah[mt][1], ah[mt][2], ah[mt][3], ra);
                ldsm4(al[mt][0], al[mt][1], al[mt][2], al[mt][3], ra + GPL * 2);
            }
#pragma unroll
            for (int nt = 0; nt < 4; nt++) {
                u32 rb = base + (u32)((2 * GPL + (wn + nt * 8 + (lane & 7)) * GSTR +
                                       ks * 16 + ((lane >> 3) & 1) * 8) * 2);
                ldsm2(bh[nt][0], bh[nt][1], rb);
                ldsm2(bl[nt][0], bl[nt][1], rb + GPL * 2);
            }
#pragma unroll
            for (int mt = 0; mt < 4; mt++)
#pragma unroll
                for (int nt = 0; nt < 4; nt++) {
                    mma16(acc[mt][nt], ah[mt], bh[nt]);
                    mma16(acc[mt][nt], ah[mt], bl[nt]);
                    mma16(acc[mt][nt], al[mt], bh[nt]);
                }
        }
        __syncthreads();
    }
    // epilogue
#pragma unroll
    for (int mt = 0; mt < 4; mt++) {
        int r0 = bm + wm + mt * 16 + (lane >> 2);
#pragma unroll
        for (int nt = 0; nt < 4; nt++) {
            int cb = bn + wn + nt * 8 + 2 * (lane & 3);
            float2 bv = *(const float2*)(bias + cb);
            float2 o0 = make_float2(acc[mt][nt][0] + bv.x, acc[mt][nt][1] + bv.y);
            float2 o1 = make_float2(acc[mt][nt][2] + bv.x, acc[mt][nt][3] + bv.y);
            *(float2*)(C + (long)r0 * N + cb) = o0;
            *(float2*)(C + (long)(r0 + 8) * N + cb) = o1;
        }
    }
}

// =====================================================================
// q/k RMS norm -> fp16 hi/lo. q folds g*4*log2(e)/||q||, k folds g*32/||k||
// =====================================================================
__global__ __launch_bounds__(256) void qk_norm(
    const float* __restrict__ qkv,
    const float* __restrict__ gq, const float* __restrict__ gk,
    __half* __restrict__ qhi, __half* __restrict__ qlo,
    __half* __restrict__ khi, __half* __restrict__ klo)
{
    long row = blockIdx.x;
    const float* p = qkv + row * (long)N3;
    int c = threadIdx.x * 4;
    float4 q4 = *(const float4*)(p + c);
    float4 k4 = *(const float4*)(p + DM + c);
    float sq = q4.x * q4.x + q4.y * q4.y + q4.z * q4.z + q4.w * q4.w;
    float sk = k4.x * k4.x + k4.y * k4.y + k4.z * k4.z + k4.w * k4.w;
#pragma unroll
    for (int m = 16; m; m >>= 1) {
        sq += __shfl_xor_sync(0xffffffffu, sq, m);
        sk += __shfl_xor_sync(0xffffffffu, sk, m);
    }
    __shared__ float2 ws[8];
    __shared__ float2 fac;
    int w = threadIdx.x >> 5;
    if ((threadIdx.x & 31) == 0) ws[w] = make_float2(sq, sk);
    __syncthreads();
    if (threadIdx.x == 0) {
        float a = 0.f, bsum = 0.f;
#pragma unroll
        for (int i = 0; i < 8; i++) { a += ws[i].x; bsum += ws[i].y; }
        fac = make_float2(5.770780163555851f / fmaxf(sqrtf(a), 1e-12f),   // 4*log2(e)
                          32.0f / fmaxf(sqrtf(bsum), 1e-12f));
    }
    __syncthreads();
    float fq = fac.x, fk = fac.y;
    float4 gq4 = *(const float4*)(gq + c);
    float4 gk4 = *(const float4*)(gk + c);
    float qs[4] = { q4.x * fq * gq4.x, q4.y * fq * gq4.y, q4.z * fq * gq4.z, q4.w * fq * gq4.w };
    float ks[4] = { k4.x * fk * gk4.x, k4.y * fk * gk4.y, k4.z * fk * gk4.z, k4.w * fk * gk4.w };
    __half qh[4], ql[4], kh[4], kl[4];
#pragma unroll
    for (int e = 0; e < 4; e++) {
        qh[e] = __float2half_rn(qs[e]); ql[e] = __float2half_rn(qs[e] - __half2float(qh[e]));
        kh[e] = __float2half_rn(ks[e]); kl[e] = __float2half_rn(ks[e] - __half2float(kh[e]));
    }
    long o = row * (long)DM + c;
    *(uint2*)(qhi + o) = *(uint2*)qh;  *(uint2*)(qlo + o) = *(uint2*)ql;
    *(uint2*)(khi + o) = *(uint2*)kh;  *(uint2*)(klo + o) = *(uint2*)kl;
}

// =====================================================================
// V transpose: qkv v-part (b,l,h*64+d) fp32 -> fp16 hi/lo [(bh*64+d)][l]
// =====================================================================
#define VT_STR 136
__global__ __launch_bounds__(256) void v_trans(
    const float* __restrict__ qkv, __half* __restrict__ vthi, __half* __restrict__ vtlo)
{
    __shared__ __half shi[64 * VT_STR], slo[64 * VT_STR];
    int bh = blockIdx.y, b = bh >> 4, h = bh & 15;
    int l0 = blockIdx.x * 128;
    int tid = threadIdx.x;
#pragma unroll
    for (int it = 0; it < 8; it++) {
        int idx = it * 256 + tid;
        int l = idx >> 4, d4 = (idx & 15) * 4;
        float4 v = *(const float4*)(qkv + ((long)(b * LL + l0 + l)) * N3 + 2 * DM + h * 64 + d4);
        float f[4] = { v.x, v.y, v.z, v.w };
#pragma unroll
        for (int e = 0; e < 4; e++) {
            __half hv = __float2half_rn(f[e]);
            __half lv = __float2half_rn(f[e] - __half2float(hv));
            shi[(d4 + e) * VT_STR + l] = hv;
            slo[(d4 + e) * VT_STR + l] = lv;
        }
    }
    __syncthreads();
#pragma unroll
    for (int it = 0; it < 8; it++) {
        int i = it * 256 + tid;
        int pl = i >> 10, j = i & 1023;
        int d = j >> 4, s = j & 15;
        uint4 v = *(uint4*)&((pl ? slo : shi)[d * VT_STR + s * 8]);
        *(uint4*)((pl ? vtlo : vthi) + ((long)bh * 64 + d) * LL + l0 + s * 8) = v;
    }
}

// =====================================================================
// HMMA flash attention with double-buffered K/V prefetch.
// Block = (128-q tile, bh). 256 thr = 8 warps (4m x 2n).
// smem (half idx): QHI 0, QLO 9216, KV0 18432, KV1 36864,
//                  PHI 55296, PLO 64512, red floats at 73728.
// =====================================================================
#define AKV0 18432
#define AKV1 36864
#define APHI 55296
#define APLO 64512
#define ARED 73728
#define AT_SMEM ((73728 + 1024) * 2)

__global__ __launch_bounds__(256) void attn_mma(
    const __half* __restrict__ qhi, const __half* __restrict__ qlo,
    const __half* __restrict__ khi, const __half* __restrict__ klo,
    const __half* __restrict__ vthi, const __half* __restrict__ vtlo,
    __half* __restrict__ ahi, __half* __restrict__ alo)
{
    extern __shared__ __half sh[];
    const u32 sb = smem_u32(sh);
    const int tid = threadIdx.x, w = tid >> 5, lane = tid & 31;
    const int bh = blockIdx.y, b = bh >> 4, hd = bh & 15;
    const int q0 = blockIdx.x * 128;
    const int wm = (w >> 1) * 32, wn = (w & 1);
    float* rmax = (float*)(sh + ARED);   // [2][128]
    float* rsum = rmax + 256;            // [2][128]

    // Q loader: plane = tid>>7, u = tid&127: s = u&7, r0 = u>>3, rows r0+16*it
    {
        const int pl = tid >> 7, u = tid & 127, s = u & 7, r0 = u >> 3;
        const __half* qb = (pl ? qlo : qhi) + ((long)(b * LL + q0 + r0)) * DM + hd * 64 + s * 8;
        u32 d0 = sb + (u32)((pl * 9216 + r0 * 72 + s * 8) * 2);
#pragma unroll
        for (int it = 0; it < 8; it++) CPA16(d0 + it * (16 * 72 * 2), qb + (long)it * 16 * DM);
        CPC();
    }
    // KV loader state: plane = tid>>6, u = tid&63: s = u&7, r0 = u>>3, rows r0+8*it
    const int kpl = tid >> 6, ku = tid & 63, kls = ku & 7, klr0 = ku >> 3;
    const __half* kvb;
    long kvstep;     // source advance per it (8 rows)
    if (kpl == 0)      { kvb = khi  + ((long)(b * LL + klr0)) * DM + hd * 64 + kls * 8; kvstep = (long)8 * DM; }
    else if (kpl == 1) { kvb = klo  + ((long)(b * LL + klr0)) * DM + hd * 64 + kls * 8; kvstep = (long)8 * DM; }
    else if (kpl == 2) { kvb = vthi + ((long)(bh * 64 + klr0)) * LL + kls * 8;          kvstep = (long)8 * LL; }
    else               { kvb = vtlo + ((long)(bh * 64 + klr0)) * LL + kls * 8;          kvstep = (long)8 * LL; }
    const long kvchunk = (kpl < 2) ? (long)64 * DM : 64;   // advance per kv chunk
    const u32 kdst0 = (u32)((kpl * 4608 + klr0 * 72 + kls * 8) * 2);

    // prologue: load chunk 0 into buf 0
#pragma unroll
    for (int it = 0; it < 8; it++) CPA16(sb + AKV0 * 2 + kdst0 + it * (8 * 72 * 2), kvb + it * kvstep);
    CPC();

    float o[2][4][4];
#pragma unroll
    for (int mt = 0; mt < 2; mt++)
#pragma unroll
        for (int dt = 0; dt < 4; dt++)
#pragma unroll
            for (int r = 0; r < 4; r++) o[mt][dt][r] = 0.f;
    float mr[4] = { -1e30f, -1e30f, -1e30f, -1e30f }, lr[4] = { 0.f, 0.f, 0.f, 0.f };

    for (int c = 0; c < 32; c++) {
        CPW(0);
        __syncthreads();   // chunk c visible; all warps done with buf (c+1)&1 (chunk c-1)
        if (c + 1 < 32) {  // prefetch chunk c+1 into the other buffer
            u32 bo = (u32)(((c + 1) & 1) ? AKV1 * 2 : AKV0 * 2);
            const __half* src = kvb + (c + 1) * kvchunk;
#pragma unroll
            for (int it = 0; it < 8; it++) CPA16(sb + bo + kdst0 + it * (8 * 72 * 2), src + it * kvstep);
            CPC();
        }
        const u32 AKVB = (u32)((c & 1) ? AKV1 : AKV0);

        // ---- S = Q K^T (hi/lo 3 products) ----
        float s[2][4][4];
#pragma unroll
        for (int mt = 0; mt < 2; mt++)
#pragma unroll
            for (int nt = 0; nt < 4; nt++)
#pragma unroll
                for (int r = 0; r < 4; r++) s[mt][nt][r] = 0.f;
#pragma unroll
        for (int ks = 0; ks < 4; ks++) {
            u32 qh_[2][4], ql_[2][4], kh_[4][2], kl_[4][2];
#pragma unroll
            for (int mt = 0; mt < 2; mt++) {
                u32 ra = sb + (u32)(((wm + mt * 16 + (lane & 15)) * 72 +
                                     ks * 16 + ((lane >> 4) & 1) * 8) * 2);
                ldsm4(qh_[mt][0], qh_[mt][1], qh_[mt][2], qh_[mt][3], ra);
                ldsm4(ql_[mt][0], ql_[mt][1], ql_[mt][2], ql_[mt][3], ra + 9216 * 2);
            }
#pragma unroll
            for (int nt = 0; nt < 4; nt++) {
                u32 rb = sb + (u32)((AKVB + (wn * 32 + nt * 8 + (lane & 7)) * 72 +
                                     ks * 16 + ((lane >> 3) & 1) * 8) * 2);
                ldsm2(kh_[nt][0], kh_[nt][1], rb);
                ldsm2(kl_[nt][0], kl_[nt][1], rb + 4608 * 2);
            }
#pragma unroll
            for (int mt = 0; mt < 2; mt++)
#pragma unroll
                for (int nt = 0; nt < 4; nt++) {
                    mma16(s[mt][nt], qh_[mt], kh_[nt]);
                    mma16(s[mt][nt], qh_[mt], kl_[nt]);
                    mma16(s[mt][nt], ql_[mt], kh_[nt]);
                }
        }

        // ---- online softmax ----
        float lmx[4], lsm[4], alpha[4];
#pragma unroll
        for (int mt = 0; mt < 2; mt++)
#pragma unroll
            for (int hh = 0; hh < 2; hh++) {
                int slot = mt * 2 + hh;
                float mx = s[mt][0][hh * 2];
#pragma unroll
                for (int nt = 0; nt < 4; nt++) {
                    mx = fmaxf(mx, s[mt][nt][hh * 2]);
                    mx = fmaxf(mx, s[mt][nt][hh * 2 + 1]);
                }
                mx = fmaxf(mx, __shfl_xor_sync(0xffffffffu, mx, 1));
                mx = fmaxf(mx, __shfl_xor_sync(0xffffffffu, mx, 2));
                lmx[slot] = mx;
                if ((lane & 3) == 0)
                    rmax[wn * 128 + wm + mt * 16 + hh * 8 + (lane >> 2)] = mx;
            }
        __syncthreads();
#pragma unroll
        for (int mt = 0; mt < 2; mt++)
#pragma unroll
            for (int hh = 0; hh < 2; hh++) {
                int slot = mt * 2 + hh;
                int rl = wm + mt * 16 + hh * 8 + (lane >> 2);
                float mn = fmaxf(mr[slot], fmaxf(lmx[slot], rmax[(1 - wn) * 128 + rl]));
                alpha[slot] = ex2f(mr[slot] - mn);
                mr[slot] = mn;
                float ssum = 0.f;
#pragma unroll
                for (int nt = 0; nt < 4; nt++) {
                    float e0 = ex2f(s[mt][nt][hh * 2] - mn);
                    float e1 = ex2f(s[mt][nt][hh * 2 + 1] - mn);
                    ssum += e0 + e1;
                    __half h0 = __float2half_rn(e0), h1 = __float2half_rn(e1);
                    __half l0 = __float2half_rn(e0 - __half2float(h0));
                    __half l1 = __float2half_rn(e1 - __half2float(h1));
                    int col = wn * 32 + nt * 8 + 2 * (lane & 3);
                    *(__half2*)(sh + APHI + rl * 72 + col) = __halves2half2(h0, h1);
                    *(__half2*)(sh + APLO + rl * 72 + col) = __halves2half2(l0, l1);
                }
                ssum += __shfl_xor_sync(0xffffffffu, ssum, 1);
                ssum += __shfl_xor_sync(0xffffffffu, ssum, 2);
                lsm[slot] = ssum;
                if ((lane & 3) == 0) rsum[wn * 128 + rl] = ssum;
            }
        __syncthreads();
#pragma unroll
        for (int mt = 0; mt < 2; mt++)
#pragma unroll
            for (int hh = 0; hh < 2; hh++) {
                int slot = mt * 2 + hh;
                int rl = wm + mt * 16 + hh * 8 + (lane >> 2);
                lr[slot] = lr[slot] * alpha[slot] + lsm[slot] + rsum[(1 - wn) * 128 + rl];
            }
        // scale O by alpha, then PV mma accumulates on top
#pragma unroll
        for (int mt = 0; mt < 2; mt++)
#pragma unroll
            for (int dt = 0; dt < 4; dt++) {
                o[mt][dt][0] *= alpha[mt * 2];     o[mt][dt][1] *= alpha[mt * 2];
                o[mt][dt][2] *= alpha[mt * 2 + 1]; o[mt][dt][3] *= alpha[mt * 2 + 1];
            }
        // ---- O += P V ----
#pragma unroll
        for (int ks = 0; ks < 4; ks++) {
            u32 ph_[2][4], pl_[2][4], vh_[4][2], vl_[4][2];
#pragma unroll
            for (int mt = 0; mt < 2; mt++) {
                u32 ra = sb + (u32)((APHI + (wm + mt * 16 + (lane & 15)) * 72 +
                                     ks * 16 + ((lane >> 4) & 1) * 8) * 2);
                ldsm4(ph_[mt][0], ph_[mt][1], ph_[mt][2], ph_[mt][3], ra);
                ldsm4(pl_[mt][0], pl_[mt][1], pl_[mt][2], pl_[mt][3], ra + 9216 * 2);
            }
#pragma unroll
            for (int dt = 0; dt < 4; dt++) {
                u32 rb = sb + (u32)((AKVB + 2 * 4608 + (wn * 32 + dt * 8 + (lane & 7)) * 72 +
                                     ks * 16 + ((lane >> 3) & 1) * 8) * 2);
                ldsm2(vh_[dt][0], vh_[dt][1], rb);
                ldsm2(vl_[dt][0], vl_[dt][1], rb + 4608 * 2);
            }
#pragma unroll
            for (int mt = 0; mt < 2; mt++)
#pragma unroll
                for (int dt = 0; dt < 4; dt++) {
                    mma16(o[mt][dt], ph_[mt], vh_[dt]);
                    mma16(o[mt][dt], ph_[mt], vl_[dt]);
                    mma16(o[mt][dt], pl_[mt], vh_[dt]);
                }
        }
    }

    // epilogue: normalize, split fp16 hi/lo, store (b, l, h*64+d)
#pragma unroll
    for (int mt = 0; mt < 2; mt++)
#pragma unroll
        for (int hh = 0; hh < 2; hh++) {
            int slot = mt * 2 + hh;
            float inv = 1.0f / lr[slot];
            int row = q0 + wm + mt * 16 + hh * 8 + (lane >> 2);
#pragma unroll
            for (int dt = 0; dt < 4; dt++) {
                int col = hd * 64 + wn * 32 + dt * 8 + 2 * (lane & 3);
                float v0 = o[mt][dt][hh * 2] * inv;
                float v1 = o[mt][dt][hh * 2 + 1] * inv;
                __half h0 = __float2half_rn(v0), h1 = __float2half_rn(v1);
                __half l0 = __float2half_rn(v0 - __half2float(h0));
                __half l1 = __float2half_rn(v1 - __half2float(h1));
                long off = ((long)(b * LL + row)) * DM + col;
                *(__half2*)(ahi + off) = __halves2half2(h0, h1);
                *(__half2*)(alo + off) = __halves2half2(l0, l1);
            }
        }
}

// =====================================================================
// Final RMS norm: out = y * g_out * 32 / max(||y||, eps)
// =====================================================================
__global__ __launch_bounds__(256) void final_norm_kernel(
    const float* __restrict__ in, const float* __restrict__ g, float* __restrict__ outp)
{
    long row = blockIdx.x;
    const float* p = in + row * (long)DM;
    int c = threadIdx.x * 4;
    float4 v = *(const float4*)(p + c);
    float s = v.x * v.x + v.y * v.y + v.z * v.z + v.w * v.w;
#pragma unroll
    for (int m = 16; m; m >>= 1) s += __shfl_xor_sync(0xffffffffu, s, m);
    __shared__ float ws[8];
    __shared__ float fac;
    int w = threadIdx.x >> 5;
    if ((threadIdx.x & 31) == 0) ws[w] = s;
    __syncthreads();
    if (threadIdx.x == 0) {
        float a = 0.f;
#pragma unroll
        for (int i = 0; i < 8; i++) a += ws[i];
        fac = 32.0f / fmaxf(sqrtf(a), 1e-12f);
    }
    __syncthreads();
    float f = fac;
    float4 g4 = *(const float4*)(g + c);
    float4 o = make_float4(v.x * f * g4.x, v.y * f * g4.y, v.z * f * g4.z, v.w * f * g4.w);
    *(float4*)(outp + row * (long)DM + c) = o;
}

// =====================================================================
// launch
// =====================================================================
extern "C" void kernel_launch(void* const* d_in, const int* in_sizes, int n_in,
                              void* d_out, int out_size)
{
    const float* x    = (const float*)d_in[0];
    const float* Wqkv = (const float*)d_in[1];
    const float* bqkv = (const float*)d_in[2];
    const float* Wout = (const float*)d_in[3];
    const float* bout = (const float*)d_in[4];
    const float* gq   = (const float*)d_in[5];
    const float* gk   = (const float*)d_in[6];
    const float* gout = (const float*)d_in[7];
    float* out = (float*)d_out;

    float *qkv, *prj;
    __half *xhi, *xlo, *whi, *wlo, *wohi, *wolo;
    __half *Qhi, *Qlo, *Khi, *Klo, *Ahi, *Alo, *Vthi, *Vtlo;
    cudaGetSymbolAddress((void**)&qkv, g_qkv);
    cudaGetSymbolAddress((void**)&prj, g_prj);
    cudaGetSymbolAddress((void**)&xhi, g_xhi);   cudaGetSymbolAddress((void**)&xlo, g_xlo);
    cudaGetSymbolAddress((void**)&whi, g_whi);   cudaGetSymbolAddress((void**)&wlo, g_wlo);
    cudaGetSymbolAddress((void**)&wohi, g_wohi); cudaGetSymbolAddress((void**)&wolo, g_wolo);
    cudaGetSymbolAddress((void**)&Qhi, g_qhi);   cudaGetSymbolAddress((void**)&Qlo, g_qlo);
    cudaGetSymbolAddress((void**)&Khi, g_khi);   cudaGetSymbolAddress((void**)&Klo, g_klo);
    cudaGetSymbolAddress((void**)&Ahi, g_ahi);   cudaGetSymbolAddress((void**)&Alo, g_alo);
    cudaGetSymbolAddress((void**)&Vthi, g_vthi); cudaGetSymbolAddress((void**)&Vtlo, g_vtlo);

    cudaFuncSetAttribute(gemm_mma, cudaFuncAttributeMaxDynamicSharedMemorySize, GM_SMEM);
    cudaFuncSetAttribute(attn_mma, cudaFuncAttributeMaxDynamicSharedMemorySize, AT_SMEM);

    // 0) fp32 -> fp16 hi/lo splits
    long n_x = (long)MR * DM / 4, n_w = (long)N3 * DM / 4, n_wo = (long)DM * DM / 4;
    conv_hilo<<<(unsigned)((n_x  + 255) / 256), 256>>>(x,    xhi,  xlo,  n_x);
    conv_hilo<<<(unsigned)((n_w  + 255) / 256), 256>>>(Wqkv, whi,  wlo,  n_w);
    conv_hilo<<<(unsigned)((n_wo + 255) / 256), 256>>>(Wout, wohi, wolo, n_wo);

    // 1) QKV projection (HMMA, 2 CTAs/SM)
    gemm_mma<<<dim3(N3 / 128, MR / 128), 256, GM_SMEM>>>(xhi, xlo, whi, wlo, bqkv, qkv, N3, DM);

    // 2) q/k norm -> fp16 hi/lo ; V -> transposed fp16 hi/lo
    qk_norm<<<MR, 256>>>(qkv, gq, gk, Qhi, Qlo, Khi, Klo);
    v_trans<<<dim3(LL / 128, BB * NH), 256>>>(qkv, Vthi, Vtlo);

    // 3) attention (HMMA, double-buffered K/V)
    attn_mma<<<dim3(LL / 128, BB * NH), 256, AT_SMEM>>>(Qhi, Qlo, Khi, Klo, Vthi, Vtlo, Ahi, Alo);

    // 4) output projection (HMMA, 2 CTAs/SM)
    gemm_mma<<<dim3(DM / 128, MR / 128), 256, GM_SMEM>>>(Ahi, Alo, wohi, wolo, bout, prj, DM, DM);

    // 5) final RMS norm -> d_out
    final_norm_kernel<<<MR, 256>>>(prj, gout, out);
}